// round 1
// baseline (speedup 1.0000x reference)
#include <cuda_runtime.h>
#include <cuda_bf16.h>
#include <cstdint>

// Problem constants
#define BATCH   16
#define C_DIM   256
#define HDIM    32
#define WDIM    32
#define N_ROWS  16384          // B*H*W
#define K_CB    8192           // codebook entries
#define Z_ELEMS 4194304        // 16*256*32*32
#define OUT_ZQ  4194304
#define OUT_LOSS_OFF 4194304
#define OUT_IDX_OFF  4194305

// Scratch (static __device__ arrays — no allocation allowed)
__device__ float  g_z2[N_ROWS];
__device__ float  g_e2[K_CB];
__device__ int    g_bestidx[N_ROWS];
__device__ double g_losspart[16384];

// ---------------------------------------------------------------------------
// z2[n] = sum_c zflat[n][c]^2, where zflat[n][c] = z[b, c, h, w], n=(b*32+h)*32+w
// warp per row, lane-strided accumulation + butterfly reduce (XLA-row-reduce-like)
// ---------------------------------------------------------------------------
__global__ void z2_kernel(const float* __restrict__ z) {
    int warp = (blockIdx.x * blockDim.x + threadIdx.x) >> 5;
    int lane = threadIdx.x & 31;
    if (warp >= N_ROWS) return;
    int b = warp >> 10;
    int r = warp & 1023;        // h*32 + w
    const float* p = z + (size_t)b * (C_DIM * HDIM * WDIM) + r;
    float s = 0.0f;
#pragma unroll
    for (int t = 0; t < 8; ++t) {
        float v = p[(size_t)(lane + 32 * t) * (HDIM * WDIM)];
        s = fmaf(v, v, s);
    }
#pragma unroll
    for (int o = 16; o > 0; o >>= 1) s += __shfl_xor_sync(0xffffffffu, s, o);
    if (lane == 0) g_z2[warp] = s;
}

// e2[k] = sum_c codebook[k][c]^2
__global__ void e2_kernel(const float* __restrict__ cb) {
    int warp = (blockIdx.x * blockDim.x + threadIdx.x) >> 5;
    int lane = threadIdx.x & 31;
    if (warp >= K_CB) return;
    const float* p = cb + (size_t)warp * C_DIM;
    float s = 0.0f;
#pragma unroll
    for (int t = 0; t < 8; ++t) {
        float v = p[lane + 32 * t];
        s = fmaf(v, v, s);
    }
#pragma unroll
    for (int o = 16; o > 0; o >>= 1) s += __shfl_xor_sync(0xffffffffu, s, o);
    if (lane == 0) g_e2[warp] = s;
}

// ---------------------------------------------------------------------------
// Main distance + argmin kernel.
// Block: 256 threads, tile 128 rows x 128 candidates, BK=16, 8x8 microtile.
// A is read directly from z (transposed-on-load): A[n][c] = z[b, c, h, w].
// d = (z2 + e2) - 2*ez  computed in fp32 exactly per the reference expression.
// Argmin with ascending-k visit order; ties resolved to lowest index.
// ---------------------------------------------------------------------------
__global__ __launch_bounds__(256) void vq_argmin_kernel(
    const float* __restrict__ z, const float* __restrict__ cb)
{
    const int tid = threadIdx.x;
    const int tx = tid & 15;    // candidate-frag index (8 cands)
    const int ty = tid >> 4;    // row-frag index (8 rows)
    const int n0 = blockIdx.x * 128;
    const int b  = n0 >> 10;
    const int r0 = n0 & 1023;   // multiple of 128, within [0,1024)
    const float* zbase = z + (size_t)b * (C_DIM * HDIM * WDIM) + r0;

    __shared__ float As[2][16 * 128];
    __shared__ float Bs[2][16 * 128];

    float best[8];
    int   bidx[8];
    float z2r[8];
#pragma unroll
    for (int i = 0; i < 8; ++i) {
        best[i] = 3.402823466e38f;
        bidx[i] = 0x7fffffff;
        z2r[i]  = g_z2[n0 + ty * 8 + i];
    }

    for (int kt = 0; kt < K_CB / 128; ++kt) {
        const int k0 = kt * 128;
        float acc[8][8];
#pragma unroll
        for (int i = 0; i < 8; ++i)
#pragma unroll
            for (int j = 0; j < 8; ++j) acc[i][j] = 0.0f;

        // ---- load chunk 0 into buffer 0 ----
        {
            const float* zc = zbase;                 // c-chunk 0
#pragma unroll
            for (int t = 0; t < 2; ++t) {
                int idx = tid + 256 * t;             // 0..511 float4 slots
                int c  = idx >> 5;                   // 0..15
                int j4 = idx & 31;                   // 0..31
                float4 v = *(const float4*)(zc + (size_t)c * (HDIM * WDIM) + j4 * 4);
                *(float4*)&As[0][c * 128 + j4 * 4] = v;
            }
#pragma unroll
            for (int t = 0; t < 2; ++t) {
                int idx = tid + 256 * t;
                int k = idx >> 2;                    // 0..127
                int q = idx & 3;                     // 0..3
                float4 v = *(const float4*)(cb + (size_t)(k0 + k) * C_DIM + q * 4);
                Bs[0][(q * 4 + 0) * 128 + k] = v.x;
                Bs[0][(q * 4 + 1) * 128 + k] = v.y;
                Bs[0][(q * 4 + 2) * 128 + k] = v.z;
                Bs[0][(q * 4 + 3) * 128 + k] = v.w;
            }
        }
        __syncthreads();

        // ---- 16 chunks of 16 c each, double buffered ----
        for (int cc = 0; cc < 16; ++cc) {
            const int cur = cc & 1;
            const int nxt = cur ^ 1;
            if (cc < 15) {
                const float* zc = zbase + (size_t)((cc + 1) * 16) * (HDIM * WDIM);
                const int cgl = (cc + 1) * 16;
#pragma unroll
                for (int t = 0; t < 2; ++t) {
                    int idx = tid + 256 * t;
                    int c  = idx >> 5;
                    int j4 = idx & 31;
                    float4 v = *(const float4*)(zc + (size_t)c * (HDIM * WDIM) + j4 * 4);
                    *(float4*)&As[nxt][c * 128 + j4 * 4] = v;
                }
#pragma unroll
                for (int t = 0; t < 2; ++t) {
                    int idx = tid + 256 * t;
                    int k = idx >> 2;
                    int q = idx & 3;
                    float4 v = *(const float4*)(cb + (size_t)(k0 + k) * C_DIM + cgl + q * 4);
                    Bs[nxt][(q * 4 + 0) * 128 + k] = v.x;
                    Bs[nxt][(q * 4 + 1) * 128 + k] = v.y;
                    Bs[nxt][(q * 4 + 2) * 128 + k] = v.z;
                    Bs[nxt][(q * 4 + 3) * 128 + k] = v.w;
                }
            }
#pragma unroll
            for (int c = 0; c < 16; ++c) {
                float a[8], bb[8];
                *(float4*)&a[0]  = *(const float4*)&As[cur][c * 128 + ty * 8];
                *(float4*)&a[4]  = *(const float4*)&As[cur][c * 128 + ty * 8 + 4];
                *(float4*)&bb[0] = *(const float4*)&Bs[cur][c * 128 + tx * 8];
                *(float4*)&bb[4] = *(const float4*)&Bs[cur][c * 128 + tx * 8 + 4];
#pragma unroll
                for (int i = 0; i < 8; ++i)
#pragma unroll
                    for (int j = 0; j < 8; ++j)
                        acc[i][j] = fmaf(a[i], bb[j], acc[i][j]);
            }
            __syncthreads();
        }

        // ---- tile epilogue: d = (z2 + e2) - 2*ez ; running argmin ----
#pragma unroll
        for (int j = 0; j < 8; ++j) {
            const int kidx = k0 + tx * 8 + j;
            const float e2v = g_e2[kidx];
#pragma unroll
            for (int i = 0; i < 8; ++i) {
                float s = z2r[i] + e2v;
                float d = s - 2.0f * acc[i][j];
                if (d < best[i]) { best[i] = d; bidx[i] = kidx; }
            }
        }
    }

    // ---- cross-thread per-row reduction (lexicographic: min d, then min idx) ----
    __syncthreads();
    float* sB = (float*)As;      // 128*16 floats = 8 KB
    int*   sI = (int*)Bs;
#pragma unroll
    for (int i = 0; i < 8; ++i) {
        sB[(ty * 8 + i) * 16 + tx] = best[i];
        sI[(ty * 8 + i) * 16 + tx] = bidx[i];
    }
    __syncthreads();
    if (tid < 128) {
        float bb = 3.402823466e38f;
        int   bi = 0x7fffffff;
#pragma unroll
        for (int t = 0; t < 16; ++t) {
            float v = sB[tid * 16 + t];
            int  id = sI[tid * 16 + t];
            if (v < bb || (v == bb && id < bi)) { bb = v; bi = id; }
        }
        g_bestidx[n0 + tid] = bi;
    }
}

// ---------------------------------------------------------------------------
// Epilogue: scrambled gather (the reference's mislabeled unpack) + per-block
// partial sums of (zp - z_q_scr)^2.
//   out[b,h2,w2,c2] = codebook[idx[n]][c],  n = b*1024 + w2*32 + (c2>>3),
//                                           c = (c2&7)*32 + h2
//   zp[b,h2,w2,c2]  = z[b, c2, h2, w2]
// ---------------------------------------------------------------------------
__global__ void epilogue_kernel(const float* __restrict__ z,
                                const float* __restrict__ cb,
                                float* __restrict__ out, int out_size)
{
    int t = blockIdx.x * 256 + threadIdx.x;
    float diff2 = 0.0f;
    if (t < Z_ELEMS) {
        int c2 = t & 255;
        int w2 = (t >> 8) & 31;
        int h2 = (t >> 13) & 31;
        int b  = t >> 18;
        int n = b * 1024 + w2 * 32 + (c2 >> 3);
        int c = (c2 & 7) * 32 + h2;
        float v = cb[(size_t)g_bestidx[n] * C_DIM + c];
        if (t < out_size) out[t] = v;
        float zp = z[(size_t)b * (C_DIM * HDIM * WDIM) + (size_t)c2 * (HDIM * WDIM) + h2 * 32 + w2];
        float d = zp - v;
        diff2 = d * d;
    }
    __shared__ double sred[256];
    sred[threadIdx.x] = (double)diff2;
    __syncthreads();
#pragma unroll
    for (int s = 128; s > 0; s >>= 1) {
        if (threadIdx.x < s) sred[threadIdx.x] += sred[threadIdx.x + s];
        __syncthreads();
    }
    if (threadIdx.x == 0) g_losspart[blockIdx.x] = sred[0];
}

// Deterministic final reduction + index emission
__global__ void finalize_kernel(float* __restrict__ out, int out_size)
{
    __shared__ double sred[256];
    double s = 0.0;
    for (int i = threadIdx.x; i < 16384; i += 256) s += g_losspart[i];
    sred[threadIdx.x] = s;
    __syncthreads();
#pragma unroll
    for (int st = 128; st > 0; st >>= 1) {
        if (threadIdx.x < st) sred[threadIdx.x] += sred[threadIdx.x + st];
        __syncthreads();
    }
    if (threadIdx.x == 0) {
        double m = sred[0] / (double)Z_ELEMS;      // codebook_loss == commitment_loss numerically
        float loss = (float)(m + 0.25 * m);
        if (OUT_LOSS_OFF < out_size) out[OUT_LOSS_OFF] = loss;
    }
    for (int i = threadIdx.x; i < N_ROWS; i += 256) {
        int o = OUT_IDX_OFF + i;
        if (o < out_size) out[o] = (float)g_bestidx[i];
    }
}

extern "C" void kernel_launch(void* const* d_in, const int* in_sizes, int n_in,
                              void* d_out, int out_size)
{
    const float* z  = (const float*)d_in[0];
    const float* cb = (const float*)d_in[1];
    float* out = (float*)d_out;

    z2_kernel<<<(N_ROWS * 32 + 255) / 256, 256>>>(z);
    e2_kernel<<<(K_CB * 32 + 255) / 256, 256>>>(cb);
    vq_argmin_kernel<<<N_ROWS / 128, 256>>>(z, cb);
    epilogue_kernel<<<Z_ELEMS / 256, 256>>>(z, cb, out, out_size);
    finalize_kernel<<<1, 256>>>(out, out_size);
}